// round 5
// baseline (speedup 1.0000x reference)
#include <cuda_runtime.h>
#include <math.h>

#define N_NODES 50000
#define N_EDGES 800000
#define DIM 128
#define CAP 64

typedef unsigned long long u64;

// Scratch (allocation-free rule: __device__ globals).
// INVARIANT: g_cnt[], g_ovf_cnt, g_done are all ZERO on entry to kernel_launch
// (zero-initialized at module load; k_agg restores them to zero every call).
__device__ float g_support[N_NODES * DIM];       // 25.6 MB
__device__ int   g_cnt[N_NODES];
__device__ int2  g_bucket[N_NODES * CAP];        // packed (col, val)
__device__ int   g_ovf[N_EDGES];                 // overflow edge ids (expected empty)
__device__ int   g_ovf_cnt;
__device__ int   g_done;

__device__ __forceinline__ u64 pk2(float a, float b) {
    u64 r; asm("mov.b64 %0, {%1,%2};" : "=l"(r) : "f"(a), "f"(b)); return r;
}
__device__ __forceinline__ u64 ffma2(u64 a, u64 b, u64 c) {
    u64 d; asm("fma.rn.f32x2 %0, %1, %2, %3;" : "=l"(d) : "l"(a), "l"(b), "l"(c)); return d;
}

// ---------------- K1: fused GEMM (FFMA2) + edge bucketing ----------------
#define GEMM_BLOCKS 782          // ceil(50000/64)
#define BUCKET_BLOCKS 1024

__global__ __launch_bounds__(128) void k_fused(const float* __restrict__ X,
                                               const float* __restrict__ W,
                                               const int* __restrict__ rows,
                                               const int* __restrict__ cols,
                                               const float* __restrict__ vals) {
    if (blockIdx.x >= GEMM_BLOCKS) {
        // ------------- bucket part (counters pre-zeroed by invariant) -------------
        int b = blockIdx.x - GEMM_BLOCKS;
        for (int e = b * 128 + threadIdx.x; e < N_EDGES; e += BUCKET_BLOCKS * 128) {
            int r = rows[e];
            int pos = atomicAdd(&g_cnt[r], 1);
            if (pos < CAP) {
                g_bucket[r * CAP + pos] = make_int2(cols[e], __float_as_int(vals[e]));
            } else {
                int o = atomicAdd(&g_ovf_cnt, 1);
                g_ovf[o] = e;   // correct fallback path (expected empty)
            }
        }
        return;
    }

    // ------------- gemm part -------------
    __shared__ u64 Wp[32 * 64];     // [k][col-pair], packed (w0,w1)   16 KB
    __shared__ u64 Xd[64 * 33];     // [row][k] duplicated (x,x), pad  16.9 KB

    const int tid  = threadIdx.x;       // 0..127
    const int rowg = tid & 7;           // 0..7
    const int colg = tid >> 3;          // 0..15
    const int rbase = blockIdx.x * 64;

    u64 acc[8][4];
    #pragma unroll
    for (int m = 0; m < 8; m++)
        #pragma unroll
        for (int j = 0; j < 4; j++) acc[m][j] = 0ull;

    for (int kc = 0; kc < 128; kc += 32) {
        // W chunk: 32 k-rows x 32 float4, 8 per thread
        #pragma unroll
        for (int p = 0; p < 8; p++) {
            int f = tid + p * 128;
            int k = f >> 5, q = f & 31;
            float4 w = ((const float4*)W)[(kc + k) * 32 + q];
            Wp[k * 64 + q * 2 + 0] = pk2(w.x, w.y);
            Wp[k * 64 + q * 2 + 1] = pk2(w.z, w.w);
        }
        // X chunk: 64 rows x 8 float4, 4 per thread (duplicated stores)
        #pragma unroll
        for (int p = 0; p < 4; p++) {
            int f = tid + p * 128;
            int r = f >> 3, q = f & 7;
            int row = rbase + r;
            float4 v = make_float4(0.f, 0.f, 0.f, 0.f);
            if (row < N_NODES) v = ((const float4*)X)[row * 32 + (kc >> 2) + q];
            Xd[r * 33 + q * 4 + 0] = pk2(v.x, v.x);
            Xd[r * 33 + q * 4 + 1] = pk2(v.y, v.y);
            Xd[r * 33 + q * 4 + 2] = pk2(v.z, v.z);
            Xd[r * 33 + q * 4 + 3] = pk2(v.w, v.w);
        }
        __syncthreads();

        #pragma unroll 8
        for (int k = 0; k < 32; k++) {
            u64 w0 = Wp[k * 64 + colg * 4 + 0];
            u64 w1 = Wp[k * 64 + colg * 4 + 1];
            u64 w2 = Wp[k * 64 + colg * 4 + 2];
            u64 w3 = Wp[k * 64 + colg * 4 + 3];
            #pragma unroll
            for (int m = 0; m < 8; m++) {
                u64 xx = Xd[(rowg + 8 * m) * 33 + k];
                acc[m][0] = ffma2(xx, w0, acc[m][0]);
                acc[m][1] = ffma2(xx, w1, acc[m][1]);
                acc[m][2] = ffma2(xx, w2, acc[m][2]);
                acc[m][3] = ffma2(xx, w3, acc[m][3]);
            }
        }
        __syncthreads();
    }

    u64* sup64 = (u64*)g_support;
    #pragma unroll
    for (int m = 0; m < 8; m++) {
        int row = rbase + rowg + 8 * m;
        if (row < N_NODES) {
            #pragma unroll
            for (int j = 0; j < 4; j++)
                sup64[row * 64 + colg * 4 + j] = acc[m][j];
        }
    }
}

// ---------------- K2: warp-per-row aggregate + inline overflow + bias/ELU ----
// Also restores the zero-invariant on g_cnt / g_ovf_cnt / g_done.
#define AGG_BLOCKS 6250          // 50000 rows / 8 warps per block (exact)

__global__ __launch_bounds__(256) void k_agg(const float* __restrict__ X,
                                             const float* __restrict__ alpha,
                                             const float* __restrict__ bias,
                                             const int* __restrict__ rows,
                                             const int* __restrict__ cols,
                                             const float* __restrict__ vals,
                                             float* __restrict__ out) {
    const int row  = (blockIdx.x * blockDim.x + threadIdx.x) >> 5;   // always < N_NODES
    const int lane = threadIdx.x & 31;

    float a0 = alpha[0], a1 = alpha[1];
    float mx = fmaxf(a0, a1);
    float e0 = __expf(a0 - mx), e1 = __expf(a1 - mx);
    float g0 = e0 / (e0 + e1);          // gate for agg
    float g1 = e1 / (e0 + e1);          // gate for residual input

    float4 x4 = ((const float4*)X)[row * 32 + lane];
    float4 accA = make_float4(g1 * x4.x, g1 * x4.y, g1 * x4.z, g1 * x4.w);
    float4 accB = make_float4(0.f, 0.f, 0.f, 0.f);

    const int nraw = g_cnt[row];
    if (lane == 0) g_cnt[row] = 0;                  // restore invariant
    const int n = nraw > CAP ? CAP : nraw;
    const int2* bk = g_bucket + row * CAP;
    const float4* sup4 = (const float4*)g_support;

    // preload entire bucket metadata (<= 64 entries) into 2 regs/lane
    int2 m0 = make_int2(0, 0), m1 = make_int2(0, 0);
    if (lane < n)      m0 = bk[lane];
    if (32 + lane < n) m1 = bk[32 + lane];

    const int n0 = n < 32 ? n : 32;
    const int c0r = (n0 + 3) & ~3;
    for (int j = 0; j < c0r; j += 4) {
        int   ca = __shfl_sync(0xffffffffu, m0.x, j + 0);
        int   cb = __shfl_sync(0xffffffffu, m0.x, j + 1);
        int   cc = __shfl_sync(0xffffffffu, m0.x, j + 2);
        int   cd = __shfl_sync(0xffffffffu, m0.x, j + 3);
        float va = g0 * __int_as_float(__shfl_sync(0xffffffffu, m0.y, j + 0));
        float vb = g0 * __int_as_float(__shfl_sync(0xffffffffu, m0.y, j + 1));
        float vc = g0 * __int_as_float(__shfl_sync(0xffffffffu, m0.y, j + 2));
        float vd = g0 * __int_as_float(__shfl_sync(0xffffffffu, m0.y, j + 3));
        float4 sa = sup4[ca * 32 + lane];
        float4 sb = sup4[cb * 32 + lane];
        float4 sc = sup4[cc * 32 + lane];
        float4 sd = sup4[cd * 32 + lane];
        accA.x += va * sa.x; accA.y += va * sa.y; accA.z += va * sa.z; accA.w += va * sa.w;
        accB.x += vb * sb.x; accB.y += vb * sb.y; accB.z += vb * sb.z; accB.w += vb * sb.w;
        accA.x += vc * sc.x; accA.y += vc * sc.y; accA.z += vc * sc.z; accA.w += vc * sc.w;
        accB.x += vd * sd.x; accB.y += vd * sd.y; accB.z += vd * sd.z; accB.w += vd * sd.w;
    }
    const int n1 = n - 32;               // may be negative
    const int c1r = n1 > 0 ? ((n1 + 3) & ~3) : 0;
    for (int j = 0; j < c1r; j += 4) {
        int   ca = __shfl_sync(0xffffffffu, m1.x, j + 0);
        int   cb = __shfl_sync(0xffffffffu, m1.x, j + 1);
        int   cc = __shfl_sync(0xffffffffu, m1.x, j + 2);
        int   cd = __shfl_sync(0xffffffffu, m1.x, j + 3);
        float va = g0 * __int_as_float(__shfl_sync(0xffffffffu, m1.y, j + 0));
        float vb = g0 * __int_as_float(__shfl_sync(0xffffffffu, m1.y, j + 1));
        float vc = g0 * __int_as_float(__shfl_sync(0xffffffffu, m1.y, j + 2));
        float vd = g0 * __int_as_float(__shfl_sync(0xffffffffu, m1.y, j + 3));
        float4 sa = sup4[ca * 32 + lane];
        float4 sb = sup4[cb * 32 + lane];
        float4 sc = sup4[cc * 32 + lane];
        float4 sd = sup4[cd * 32 + lane];
        accA.x += va * sa.x; accA.y += va * sa.y; accA.z += va * sa.z; accA.w += va * sa.w;
        accB.x += vb * sb.x; accB.y += vb * sb.y; accB.z += vb * sb.z; accB.w += vb * sb.w;
        accA.x += vc * sc.x; accA.y += vc * sc.y; accA.z += vc * sc.z; accA.w += vc * sc.w;
        accB.x += vd * sd.x; accB.y += vd * sd.y; accB.z += vd * sd.z; accB.w += vd * sd.w;
    }

    // inline overflow fallback: scan global overflow list (expected 0 entries)
    if (nraw > CAP) {
        int nov = g_ovf_cnt;
        for (int i = 0; i < nov; i++) {
            int e = g_ovf[i];
            if (rows[e] == row) {
                int c = cols[e];
                float v = g0 * vals[e];
                float4 s = sup4[c * 32 + lane];
                accA.x += v * s.x; accA.y += v * s.y; accA.z += v * s.z; accA.w += v * s.w;
            }
        }
    }

    float4 acc;
    acc.x = accA.x + accB.x; acc.y = accA.y + accB.y;
    acc.z = accA.z + accB.z; acc.w = accA.w + accB.w;

    // bias + ELU
    float4 b = ((const float4*)bias)[lane];
    acc.x += b.x; acc.y += b.y; acc.z += b.z; acc.w += b.w;
    acc.x = acc.x > 0.f ? acc.x : expm1f(acc.x);
    acc.y = acc.y > 0.f ? acc.y : expm1f(acc.y);
    acc.z = acc.z > 0.f ? acc.z : expm1f(acc.z);
    acc.w = acc.w > 0.f ? acc.w : expm1f(acc.w);
    ((float4*)out)[row * 32 + lane] = acc;

    // last-finishing block restores g_ovf_cnt / g_done to zero
    __syncthreads();
    if (threadIdx.x == 0) {
        __threadfence();
        int t = atomicAdd(&g_done, 1);
        if (t == AGG_BLOCKS - 1) {
            g_ovf_cnt = 0;
            g_done = 0;
            __threadfence();
        }
    }
}

extern "C" void kernel_launch(void* const* d_in, const int* in_sizes, int n_in,
                              void* d_out, int out_size) {
    const float* X     = (const float*)d_in[0];   // inputs  [50000,128]
    const float* W     = (const float*)d_in[1];   // weight  [128,128]
    const float* bias  = (const float*)d_in[2];   // bias    [128]
    const float* alpha = (const float*)d_in[3];   // alpha   [2]
    const float* vals  = (const float*)d_in[4];   // adj_vals [800000]
    const int*   rows  = (const int*)d_in[5];     // adj_rows [800000]
    const int*   cols  = (const int*)d_in[6];     // adj_cols [800000]
    float* out = (float*)d_out;

    k_fused<<<GEMM_BLOCKS + BUCKET_BLOCKS, 128>>>(X, W, rows, cols, vals);
    k_agg  <<<AGG_BLOCKS, 256>>>(X, alpha, bias, rows, cols, vals, out);
}

// round 6
// speedup vs baseline: 1.9485x; 1.9485x over previous
#include <cuda_runtime.h>
#include <math.h>

#define N_NODES 50000
#define N_EDGES 800000
#define DIM 128
#define CAP 64

typedef unsigned long long u64;

// Scratch (allocation-free rule: __device__ globals)
__device__ float g_support[N_NODES * DIM];       // 25.6 MB
__device__ int   g_cnt[N_NODES];
__device__ int2  g_bucket[N_NODES * CAP];        // packed (col, val)
__device__ int   g_ovf[N_EDGES];                 // overflow edge ids (expected empty)
__device__ int   g_ovf_cnt;

__device__ __forceinline__ u64 pk2(float a, float b) {
    u64 r; asm("mov.b64 %0, {%1,%2};" : "=l"(r) : "f"(a), "f"(b)); return r;
}
__device__ __forceinline__ u64 ffma2(u64 a, u64 b, u64 c) {
    u64 d; asm("fma.rn.f32x2 %0, %1, %2, %3;" : "=l"(d) : "l"(a), "l"(b), "l"(c)); return d;
}

// ---------------- K0: zero counters ----------------
__global__ void k_zero() {
    int i = blockIdx.x * blockDim.x + threadIdx.x;
    if (i < N_NODES) g_cnt[i] = 0;
    if (i == 0) g_ovf_cnt = 0;
}

// ---------------- K1: GEMM, FFMA2 with balanced smem traffic ----------------
// 128 threads, 64-row x 128-col tile. Per thread: 8 rows x 8 cols (32 u64 acc).
// W in smem packed u64 (LDS.64), X in smem SCALAR (LDS.32 + 1 MOV pack) so LDS
// bytes/k/block = 8192B = 64 cyc = FFMA2 issue floor (balanced, ~2x scalar gemm).
#define GEMM_BLOCKS 782          // ceil(50000/64)

__global__ __launch_bounds__(128) void k_gemm(const float* __restrict__ X,
                                              const float* __restrict__ W) {
    __shared__ u64   Wp[32 * 64];    // [k][col-pair] packed (w0,w1)  16 KB
    __shared__ float Xs[64 * 36];    // [row][k] scalar, pad 36       9.2 KB

    const int tid  = threadIdx.x;       // 0..127
    const int rowg = tid & 7;           // 0..7
    const int colg = tid >> 3;          // 0..15
    const int rbase = blockIdx.x * 64;

    u64 acc[8][4];
    #pragma unroll
    for (int m = 0; m < 8; m++)
        #pragma unroll
        for (int j = 0; j < 4; j++) acc[m][j] = 0ull;

    for (int kc = 0; kc < 128; kc += 32) {
        // W chunk: 32 k-rows x 32 float4 = 1024 float4, 8 per thread
        #pragma unroll
        for (int p = 0; p < 8; p++) {
            int f = tid + p * 128;
            int k = f >> 5, q = f & 31;
            float4 w = ((const float4*)W)[(kc + k) * 32 + q];
            Wp[k * 64 + q * 2 + 0] = pk2(w.x, w.y);
            Wp[k * 64 + q * 2 + 1] = pk2(w.z, w.w);
        }
        // X chunk: 64 rows x 8 float4 = 512 float4, 4 per thread (scalar store, aligned)
        #pragma unroll
        for (int p = 0; p < 4; p++) {
            int f = tid + p * 128;
            int r = f >> 3, q = f & 7;
            int row = rbase + r;
            float4 v = make_float4(0.f, 0.f, 0.f, 0.f);
            if (row < N_NODES) v = ((const float4*)X)[row * 32 + (kc >> 2) + q];
            *(float4*)&Xs[r * 36 + q * 4] = v;     // 36*4B rows: 16B-aligned, conflict-free
        }
        __syncthreads();

        #pragma unroll 4
        for (int k = 0; k < 32; k++) {
            u64 w0 = Wp[k * 64 + colg * 4 + 0];
            u64 w1 = Wp[k * 64 + colg * 4 + 1];
            u64 w2 = Wp[k * 64 + colg * 4 + 2];
            u64 w3 = Wp[k * 64 + colg * 4 + 3];
            #pragma unroll
            for (int m = 0; m < 8; m++) {
                float x = Xs[(rowg + 8 * m) * 36 + k];
                u64 xx = pk2(x, x);
                acc[m][0] = ffma2(xx, w0, acc[m][0]);
                acc[m][1] = ffma2(xx, w1, acc[m][1]);
                acc[m][2] = ffma2(xx, w2, acc[m][2]);
                acc[m][3] = ffma2(xx, w3, acc[m][3]);
            }
        }
        __syncthreads();
    }

    u64* sup64 = (u64*)g_support;
    #pragma unroll
    for (int m = 0; m < 8; m++) {
        int row = rbase + rowg + 8 * m;
        if (row < N_NODES) {
            #pragma unroll
            for (int j = 0; j < 4; j++)
                sup64[row * 64 + colg * 4 + j] = acc[m][j];
        }
    }
}

// ---------------- K2: bucket edges by destination row (packed col+val) -------
__global__ void k_bucket(const int* __restrict__ rows,
                         const int* __restrict__ cols,
                         const float* __restrict__ vals) {
    int e = blockIdx.x * blockDim.x + threadIdx.x;
    if (e >= N_EDGES) return;
    int r = rows[e];
    int pos = atomicAdd(&g_cnt[r], 1);
    if (pos < CAP) {
        g_bucket[r * CAP + pos] = make_int2(cols[e], __float_as_int(vals[e]));
    } else {
        int o = atomicAdd(&g_ovf_cnt, 1);
        g_ovf[o] = e;   // correct fallback path (expected empty)
    }
}

// ---------------- K3: warp-per-row aggregate + gated residual + fused ELU ----
// (exact round-2 body: 32 regs, high occupancy — proven fastest variant)
__global__ __launch_bounds__(256) void k_agg(const float* __restrict__ X,
                                             const float* __restrict__ alpha,
                                             const float* __restrict__ bias,
                                             float* __restrict__ out) {
    int row  = (blockIdx.x * blockDim.x + threadIdx.x) >> 5;
    int lane = threadIdx.x & 31;
    if (row >= N_NODES) return;

    float a0 = alpha[0], a1 = alpha[1];
    float mx = fmaxf(a0, a1);
    float e0 = __expf(a0 - mx), e1 = __expf(a1 - mx);
    float g0 = e0 / (e0 + e1);          // gate for agg
    float g1 = e1 / (e0 + e1);          // gate for residual input

    float4 x4 = ((const float4*)X)[row * 32 + lane];
    float4 acc = make_float4(g1 * x4.x, g1 * x4.y, g1 * x4.z, g1 * x4.w);

    int n = g_cnt[row];
    if (n > CAP) n = CAP;
    const int2* bk = g_bucket + row * CAP;
    const float4* sup4 = (const float4*)g_support;

    for (int base = 0; base < n; base += 32) {
        int2 meta = make_int2(0, 0);
        if (base + lane < n) meta = bk[base + lane];
        int cnt = n - base; if (cnt > 32) cnt = 32;
        int c4 = (cnt + 3) & ~3;
        for (int j = 0; j < c4; j += 4) {
            int   c0 = __shfl_sync(0xffffffffu, meta.x, j + 0);
            int   c1 = __shfl_sync(0xffffffffu, meta.x, j + 1);
            int   c2 = __shfl_sync(0xffffffffu, meta.x, j + 2);
            int   c3 = __shfl_sync(0xffffffffu, meta.x, j + 3);
            float v0 = g0 * __int_as_float(__shfl_sync(0xffffffffu, meta.y, j + 0));
            float v1 = g0 * __int_as_float(__shfl_sync(0xffffffffu, meta.y, j + 1));
            float v2 = g0 * __int_as_float(__shfl_sync(0xffffffffu, meta.y, j + 2));
            float v3 = g0 * __int_as_float(__shfl_sync(0xffffffffu, meta.y, j + 3));
            float4 s0 = sup4[c0 * 32 + lane];
            float4 s1 = sup4[c1 * 32 + lane];
            float4 s2 = sup4[c2 * 32 + lane];
            float4 s3 = sup4[c3 * 32 + lane];
            acc.x += v0 * s0.x; acc.y += v0 * s0.y; acc.z += v0 * s0.z; acc.w += v0 * s0.w;
            acc.x += v1 * s1.x; acc.y += v1 * s1.y; acc.z += v1 * s1.z; acc.w += v1 * s1.w;
            acc.x += v2 * s2.x; acc.y += v2 * s2.y; acc.z += v2 * s2.z; acc.w += v2 * s2.w;
            acc.x += v3 * s3.x; acc.y += v3 * s3.y; acc.z += v3 * s3.z; acc.w += v3 * s3.w;
        }
    }

    if (g_ovf_cnt == 0) {
        // fused bias + ELU epilogue (normal path)
        float4 b = ((const float4*)bias)[lane];
        acc.x += b.x; acc.y += b.y; acc.z += b.z; acc.w += b.w;
        acc.x = acc.x > 0.f ? acc.x : expm1f(acc.x);
        acc.y = acc.y > 0.f ? acc.y : expm1f(acc.y);
        acc.z = acc.z > 0.f ? acc.z : expm1f(acc.z);
        acc.w = acc.w > 0.f ? acc.w : expm1f(acc.w);
    }
    ((float4*)out)[row * 32 + lane] = acc;
}

// ---------------- K3b: overflow fallback (atomicAdd; expected no work) -------
__global__ void k_ovf(const float* __restrict__ alpha,
                      const float* __restrict__ vals,
                      const int* __restrict__ rows,
                      const int* __restrict__ cols,
                      float* __restrict__ out) {
    int nov = g_ovf_cnt;
    if (nov <= 0) return;
    float a0 = alpha[0], a1 = alpha[1];
    float mx = fmaxf(a0, a1);
    float e0 = __expf(a0 - mx), e1 = __expf(a1 - mx);
    float g0 = e0 / (e0 + e1);

    int warp   = (blockIdx.x * blockDim.x + threadIdx.x) >> 5;
    int lane   = threadIdx.x & 31;
    int nwarps = (gridDim.x * blockDim.x) >> 5;
    for (int i = warp; i < nov; i += nwarps) {
        int e = g_ovf[i];
        int r = rows[e], c = cols[e];
        float v = g0 * vals[e];
        #pragma unroll
        for (int q = 0; q < 4; q++)
            atomicAdd(&out[r * DIM + lane * 4 + q],
                      v * g_support[c * DIM + lane * 4 + q]);
    }
}

// ---------------- K4: bias + ELU (only runs if overflow path was taken) ------
__global__ void k_elu(const float* __restrict__ bias, float* __restrict__ out) {
    if (g_ovf_cnt == 0) return;   // normal path: already applied in k_agg
    int i = blockIdx.x * blockDim.x + threadIdx.x;
    if (i >= N_NODES * 32) return;
    float4 b = ((const float4*)bias)[i & 31];
    float4 v = ((float4*)out)[i];
    v.x += b.x; v.y += b.y; v.z += b.z; v.w += b.w;
    v.x = v.x > 0.f ? v.x : expm1f(v.x);
    v.y = v.y > 0.f ? v.y : expm1f(v.y);
    v.z = v.z > 0.f ? v.z : expm1f(v.z);
    v.w = v.w > 0.f ? v.w : expm1f(v.w);
    ((float4*)out)[i] = v;
}

extern "C" void kernel_launch(void* const* d_in, const int* in_sizes, int n_in,
                              void* d_out, int out_size) {
    const float* X     = (const float*)d_in[0];   // inputs  [50000,128]
    const float* W     = (const float*)d_in[1];   // weight  [128,128]
    const float* bias  = (const float*)d_in[2];   // bias    [128]
    const float* alpha = (const float*)d_in[3];   // alpha   [2]
    const float* vals  = (const float*)d_in[4];   // adj_vals [800000]
    const int*   rows  = (const int*)d_in[5];     // adj_rows [800000]
    const int*   cols  = (const int*)d_in[6];     // adj_cols [800000]
    float* out = (float*)d_out;

    k_zero  <<<(N_NODES + 255) / 256, 256>>>();
    k_gemm  <<<GEMM_BLOCKS, 128>>>(X, W);
    k_bucket<<<(N_EDGES + 255) / 256, 256>>>(rows, cols, vals);
    k_agg   <<<(N_NODES + 7) / 8, 256>>>(X, alpha, bias, out);
    k_ovf   <<<64, 256>>>(alpha, vals, rows, cols, out);
    k_elu   <<<(N_NODES * 32 + 255) / 256, 256>>>(bias, out);
}

// round 8
// speedup vs baseline: 2.1123x; 1.0841x over previous
#include <cuda_runtime.h>
#include <cuda_bf16.h>
#include <math.h>
#include <stdint.h>

#define N_NODES 50000
#define N_EDGES 800000
#define DIM 128
#define CAP 64

// Scratch (allocation-free rule: __device__ globals). Zero-initialized at load;
// g_cnt / g_ovf_cnt / g_fix_done restored to zero every call.
__device__ float g_support[N_NODES * DIM];
__device__ int   g_cnt[N_NODES];
__device__ int2  g_bucket[N_NODES * CAP];
__device__ int   g_ovf[N_EDGES];
__device__ int   g_ovf_cnt;
__device__ int   g_fix_done;

// m16n8k16 row.col bf16 MMA, f32 accumulate-in-place
__device__ __forceinline__ void mma_bf16(float* d, const uint32_t* a, const uint32_t* b) {
    asm volatile(
        "mma.sync.aligned.m16n8k16.row.col.f32.bf16.bf16.f32 "
        "{%0,%1,%2,%3}, {%4,%5,%6,%7}, {%8,%9}, {%0,%1,%2,%3};"
        : "+f"(d[0]), "+f"(d[1]), "+f"(d[2]), "+f"(d[3])
        : "r"(a[0]), "r"(a[1]), "r"(a[2]), "r"(a[3]), "r"(b[0]), "r"(b[1]));
}

// ---------------- K1: HMMA bf16-split GEMM (+ fused counter zeroing) ----------
// support = X @ W via (Xhi+Xlo)(Whi+Wlo), dropping Xlo*Wlo (error ~2^-18).
// Block: 128 rows x 128 cols, 256 threads (8 warps, warp tile 32m x 64n).
#define GEMM_BLOCKS 391           // ceil(50000/128)
#define XS 136                    // bf16 row stride: (g*68+tig) mod 32 = g*4+tig -> conflict-free
#define SMEM_GEMM (4 * 128 * XS * 2)

__global__ __launch_bounds__(256, 1) void k_gemm_mma(const float* __restrict__ X,
                                                     const float* __restrict__ W) {
    extern __shared__ __nv_bfloat16 sm[];
    __nv_bfloat16* Xh = sm;                    // [128][XS]
    __nv_bfloat16* Xl = Xh + 128 * XS;
    __nv_bfloat16* Bh = Xl + 128 * XS;         // Wt: [n][k] = W[k][n]
    __nv_bfloat16* Bl = Bh + 128 * XS;

    const int tid   = threadIdx.x;
    const int rbase = blockIdx.x * 128;

    // fused: zero bucket counters (391*256 = 100096 >= N_NODES)
    {
        int g = blockIdx.x * 256 + tid;
        if (g < N_NODES) g_cnt[g] = 0;
        if (g == 0) { g_ovf_cnt = 0; g_fix_done = 0; }
    }

    // ---- convert W -> Bh/Bl transposed ----
    for (int idx = tid; idx < 128 * 128; idx += 256) {
        int k = idx >> 7, n = idx & 127;
        float w = W[idx];
        __nv_bfloat16 hi = __float2bfloat16(w);
        Bh[n * XS + k] = hi;
        Bl[n * XS + k] = __float2bfloat16(w - __bfloat162float(hi));
    }
    // ---- convert X rows -> Xh/Xl ----
    for (int f = tid; f < 128 * 32; f += 256) {
        int r = f >> 5, q = f & 31;            // q: float4 index within row
        int row = rbase + r;
        float4 v = make_float4(0.f, 0.f, 0.f, 0.f);
        if (row < N_NODES) v = ((const float4*)X)[row * 32 + q];
        float hx = __bfloat162float(__float2bfloat16(v.x));
        float hy = __bfloat162float(__float2bfloat16(v.y));
        float hz = __bfloat162float(__float2bfloat16(v.z));
        float hw = __bfloat162float(__float2bfloat16(v.w));
        __nv_bfloat162* ph = (__nv_bfloat162*)&Xh[r * XS + q * 4];
        __nv_bfloat162* pl = (__nv_bfloat162*)&Xl[r * XS + q * 4];
        ph[0] = __floats2bfloat162_rn(hx, hy);
        ph[1] = __floats2bfloat162_rn(hz, hw);
        pl[0] = __floats2bfloat162_rn(v.x - hx, v.y - hy);
        pl[1] = __floats2bfloat162_rn(v.z - hz, v.w - hw);
    }
    __syncthreads();

    const int warp = tid >> 5, lane = tid & 31;
    const int g = lane >> 2, tig = lane & 3;
    const int wm = warp & 3;                   // m offset = wm*32
    const int wn = warp >> 2;                  // n offset = wn*64

    float acc[2][8][4];
    #pragma unroll
    for (int mt = 0; mt < 2; mt++)
        #pragma unroll
        for (int nt = 0; nt < 8; nt++)
            #pragma unroll
            for (int j = 0; j < 4; j++) acc[mt][nt][j] = 0.f;

    #pragma unroll 2
    for (int ks = 0; ks < 8; ks++) {
        const int kb = ks * 16 + tig * 2;
        uint32_t ah[2][4], al[2][4];
        #pragma unroll
        for (int mt = 0; mt < 2; mt++) {
            int r0 = wm * 32 + mt * 16 + g;
            ah[mt][0] = *(uint32_t*)&Xh[ r0      * XS + kb    ];
            ah[mt][1] = *(uint32_t*)&Xh[(r0 + 8) * XS + kb    ];
            ah[mt][2] = *(uint32_t*)&Xh[ r0      * XS + kb + 8];
            ah[mt][3] = *(uint32_t*)&Xh[(r0 + 8) * XS + kb + 8];
            al[mt][0] = *(uint32_t*)&Xl[ r0      * XS + kb    ];
            al[mt][1] = *(uint32_t*)&Xl[(r0 + 8) * XS + kb    ];
            al[mt][2] = *(uint32_t*)&Xl[ r0      * XS + kb + 8];
            al[mt][3] = *(uint32_t*)&Xl[(r0 + 8) * XS + kb + 8];
        }
        uint32_t bh[8][2], bl[8][2];
        #pragma unroll
        for (int nt = 0; nt < 8; nt++) {
            int n0 = wn * 64 + nt * 8 + g;
            bh[nt][0] = *(uint32_t*)&Bh[n0 * XS + kb    ];
            bh[nt][1] = *(uint32_t*)&Bh[n0 * XS + kb + 8];
            bl[nt][0] = *(uint32_t*)&Bl[n0 * XS + kb    ];
            bl[nt][1] = *(uint32_t*)&Bl[n0 * XS + kb + 8];
        }
        #pragma unroll
        for (int mt = 0; mt < 2; mt++)
            #pragma unroll
            for (int nt = 0; nt < 8; nt++) {
                mma_bf16(acc[mt][nt], ah[mt], bh[nt]);
                mma_bf16(acc[mt][nt], ah[mt], bl[nt]);
                mma_bf16(acc[mt][nt], al[mt], bh[nt]);
            }
    }

    // epilogue: c0,c1 -> (row, col..col+1); c2,c3 -> (row+8, col..col+1)
    #pragma unroll
    for (int mt = 0; mt < 2; mt++) {
        #pragma unroll
        for (int nt = 0; nt < 8; nt++) {
            int row = rbase + wm * 32 + mt * 16 + g;
            int col = wn * 64 + nt * 8 + tig * 2;
            if (row < N_NODES)
                *(float2*)&g_support[row * DIM + col] =
                    make_float2(acc[mt][nt][0], acc[mt][nt][1]);
            if (row + 8 < N_NODES)
                *(float2*)&g_support[(row + 8) * DIM + col] =
                    make_float2(acc[mt][nt][2], acc[mt][nt][3]);
        }
    }
}

// ---------------- K2: bucket edges by destination row ----------------
__global__ void k_bucket(const int* __restrict__ rows,
                         const int* __restrict__ cols,
                         const float* __restrict__ vals) {
    int e = blockIdx.x * blockDim.x + threadIdx.x;
    if (e >= N_EDGES) return;
    int r = rows[e];
    int pos = atomicAdd(&g_cnt[r], 1);
    if (pos < CAP) {
        g_bucket[r * CAP + pos] = make_int2(cols[e], __float_as_int(vals[e]));
    } else {
        int o = atomicAdd(&g_ovf_cnt, 1);
        g_ovf[o] = e;
    }
}

// ---------------- K3: warp-per-row aggregate (proven R2 body) ----------------
__global__ __launch_bounds__(256) void k_agg(const float* __restrict__ X,
                                             const float* __restrict__ alpha,
                                             const float* __restrict__ bias,
                                             float* __restrict__ out) {
    int row  = (blockIdx.x * blockDim.x + threadIdx.x) >> 5;
    int lane = threadIdx.x & 31;
    if (row >= N_NODES) return;

    float a0 = alpha[0], a1 = alpha[1];
    float mx = fmaxf(a0, a1);
    float e0 = __expf(a0 - mx), e1 = __expf(a1 - mx);
    float g0 = e0 / (e0 + e1);
    float g1 = e1 / (e0 + e1);

    float4 x4 = ((const float4*)X)[row * 32 + lane];
    float4 acc = make_float4(g1 * x4.x, g1 * x4.y, g1 * x4.z, g1 * x4.w);

    int n = g_cnt[row];
    if (n > CAP) n = CAP;
    const int2* bk = g_bucket + row * CAP;
    const float4* sup4 = (const float4*)g_support;

    for (int base = 0; base < n; base += 32) {
        int2 meta = make_int2(0, 0);
        if (base + lane < n) meta = bk[base + lane];
        int cnt = n - base; if (cnt > 32) cnt = 32;
        int c4 = (cnt + 3) & ~3;
        for (int j = 0; j < c4; j += 4) {
            int   c0 = __shfl_sync(0xffffffffu, meta.x, j + 0);
            int   c1 = __shfl_sync(0xffffffffu, meta.x, j + 1);
            int   c2 = __shfl_sync(0xffffffffu, meta.x, j + 2);
            int   c3 = __shfl_sync(0xffffffffu, meta.x, j + 3);
            float v0 = g0 * __int_as_float(__shfl_sync(0xffffffffu, meta.y, j + 0));
            float v1 = g0 * __int_as_float(__shfl_sync(0xffffffffu, meta.y, j + 1));
            float v2 = g0 * __int_as_float(__shfl_sync(0xffffffffu, meta.y, j + 2));
            float v3 = g0 * __int_as_float(__shfl_sync(0xffffffffu, meta.y, j + 3));
            float4 s0 = sup4[c0 * 32 + lane];
            float4 s1 = sup4[c1 * 32 + lane];
            float4 s2 = sup4[c2 * 32 + lane];
            float4 s3 = sup4[c3 * 32 + lane];
            acc.x += v0 * s0.x; acc.y += v0 * s0.y; acc.z += v0 * s0.z; acc.w += v0 * s0.w;
            acc.x += v1 * s1.x; acc.y += v1 * s1.y; acc.z += v1 * s1.z; acc.w += v1 * s1.w;
            acc.x += v2 * s2.x; acc.y += v2 * s2.y; acc.z += v2 * s2.z; acc.w += v2 * s2.w;
            acc.x += v3 * s3.x; acc.y += v3 * s3.y; acc.z += v3 * s3.z; acc.w += v3 * s3.w;
        }
    }

    if (g_ovf_cnt == 0) {   // normal path: fused bias + ELU
        float4 b = ((const float4*)bias)[lane];
        acc.x += b.x; acc.y += b.y; acc.z += b.z; acc.w += b.w;
        acc.x = acc.x > 0.f ? acc.x : expm1f(acc.x);
        acc.y = acc.y > 0.f ? acc.y : expm1f(acc.y);
        acc.z = acc.z > 0.f ? acc.z : expm1f(acc.z);
        acc.w = acc.w > 0.f ? acc.w : expm1f(acc.w);
    }
    ((float4*)out)[row * 32 + lane] = acc;
}

// ---------------- K4: overflow fixup (guard-exit on normal path) -------------
__global__ void k_fixup(const float* __restrict__ alpha,
                        const float* __restrict__ vals,
                        const int* __restrict__ rows,
                        const int* __restrict__ cols,
                        const float* __restrict__ bias,
                        float* __restrict__ out) {
    if (g_ovf_cnt == 0) return;
    __shared__ int s_last;

    float a0 = alpha[0], a1 = alpha[1];
    float mx = fmaxf(a0, a1);
    float e0 = __expf(a0 - mx), e1 = __expf(a1 - mx);
    float g0 = e0 / (e0 + e1);

    int nov  = g_ovf_cnt;
    int warp = (blockIdx.x * blockDim.x + threadIdx.x) >> 5;
    int lane = threadIdx.x & 31;
    int nwarps = (gridDim.x * blockDim.x) >> 5;
    for (int i = warp; i < nov; i += nwarps) {
        int e = g_ovf[i];
        int r = rows[e], c = cols[e];
        float v = g0 * vals[e];
        #pragma unroll
        for (int q = 0; q < 4; q++)
            atomicAdd(&out[r * DIM + lane * 4 + q],
                      v * g_support[c * DIM + lane * 4 + q]);
    }
    __syncthreads();
    if (threadIdx.x == 0) {
        __threadfence();
        s_last = (atomicAdd(&g_fix_done, 1) == (int)gridDim.x - 1);
    }
    __syncthreads();
    if (s_last) {   // last block applies bias + ELU everywhere (rare path)
        for (int i = threadIdx.x; i < N_NODES * 32; i += blockDim.x) {
            float4 b = ((const float4*)bias)[i & 31];
            float4 v = ((float4*)out)[i];
            v.x += b.x; v.y += b.y; v.z += b.z; v.w += b.w;
            v.x = v.x > 0.f ? v.x : expm1f(v.x);
            v.y = v.y > 0.f ? v.y : expm1f(v.y);
            v.z = v.z > 0.f ? v.z : expm1f(v.z);
            v.w = v.w > 0.f ? v.w : expm1f(v.w);
            ((float4*)out)[i] = v;
        }
        if (threadIdx.x == 0) g_fix_done = 0;
    }
}

extern "C" void kernel_launch(void* const* d_in, const int* in_sizes, int n_in,
                              void* d_out, int out_size) {
    const float* X     = (const float*)d_in[0];
    const float* W     = (const float*)d_in[1];
    const float* bias  = (const float*)d_in[2];
    const float* alpha = (const float*)d_in[3];
    const float* vals  = (const float*)d_in[4];
    const int*   rows  = (const int*)d_in[5];
    const int*   cols  = (const int*)d_in[6];
    float* out = (float*)d_out;

    static bool attr_set = false;
    if (!attr_set) {
        cudaFuncSetAttribute(k_gemm_mma, cudaFuncAttributeMaxDynamicSharedMemorySize, SMEM_GEMM);
        attr_set = true;
    }

    k_gemm_mma<<<GEMM_BLOCKS, 256, SMEM_GEMM>>>(X, W);
    k_bucket  <<<(N_EDGES + 255) / 256, 256>>>(rows, cols, vals);
    k_agg     <<<(N_NODES + 7) / 8, 256>>>(X, alpha, bias, out);
    k_fixup   <<<64, 256>>>(alpha, vals, rows, cols, bias, out);
}